// round 10
// baseline (speedup 1.0000x reference)
#include <cuda_runtime.h>
#include <cstdint>

#define N_ROWS 8192
#define F_COLS 8192
#define K_SEL  2867u
#define KR_SAMP 717u   /* ceil(K_SEL * 2048 / 8192) */

// Scratch (static __device__ arrays — allocation-free per harness rules)
__device__ __align__(16) float g_boost[F_COLS];
__device__ __align__(16) float g_rboost[F_COLS];
// Bit-interleaved positivity mask: word index wc in [0,256):
//   group = wc>>2, b = wc&3; bit i of word <-> column group*128 + 4*i + b
// stored transposed: g_mask[wc * N_ROWS + row]
__device__ unsigned g_mask[256 * N_ROWS];

// ---------------------------------------------------------------------------
// Kernel 1: boost = exp(BETA*(target - duty_cycle)) and its reciprocal
// ---------------------------------------------------------------------------
__global__ void boost_kernel(const float* __restrict__ dc) {
    int j = blockIdx.x * blockDim.x + threadIdx.x;
    if (j < F_COLS) {
        const float target = 2867.0f / 8192.0f;   // exact dyadic
        float b = expf(1.5f * (target - dc[j]));
        g_boost[j]  = b;
        g_rboost[j] = 1.0f / b;
    }
}

// ---------------------------------------------------------------------------
// Packed-u16 histogram helpers: 2048 bins live in 1024 u32 words.
// Max per-bin count here is 8192 < 65535, so halves never carry.
// ---------------------------------------------------------------------------
__device__ __forceinline__ void hinc(unsigned* __restrict__ h32, unsigned bin) {
    atomicAdd(&h32[bin >> 1], (bin & 1u) ? 0x10000u : 1u);
}
__device__ __forceinline__ unsigned hget(const unsigned* __restrict__ h32,
                                         unsigned bin) {
    return (h32[bin >> 1] >> ((bin & 1u) * 16u)) & 0xFFFFu;
}

// ---------------------------------------------------------------------------
// Radix-select over a packed 2048-bin histogram: find bin B with
//   count(bins > B) < kr <= count(bins >= B);  writes B and residual rank.
// Defined for all inputs: if kr exceeds the histogram total, returns bin 0
// with residual rank 1 (callers' guards make this unreachable in practice).
// ---------------------------------------------------------------------------
__device__ __forceinline__ void select_bin_p(const unsigned* __restrict__ h32,
                                             unsigned* __restrict__ part,
                                             unsigned kr,
                                             volatile unsigned* sh_bin,
                                             volatile unsigned* sh_kr) {
    int t = threadIdx.x;
    if (t == 0) { *sh_bin = 0; *sh_kr = 1; }   // defined default
    // level 1: thread t sums bins 8t..8t+7 (= words 4t..4t+3)
    unsigned s = 0;
#pragma unroll
    for (int i = 0; i < 4; ++i) {
        unsigned wv = h32[t * 4 + i];
        s += (wv & 0xFFFFu) + (wv >> 16);
    }
    part[t] = s;
    __syncthreads();

    if (t < 32) {
        unsigned c = 0;
#pragma unroll
        for (int i = 0; i < 8; ++i) c += part[t * 8 + i];
        unsigned v = c;
#pragma unroll
        for (int off = 1; off < 32; off <<= 1) {
            unsigned u = __shfl_down_sync(0xffffffffu, v, off);
            if (t + off < 32) v += u;
        }
        unsigned ab = __shfl_down_sync(0xffffffffu, v, 1);
        if (t == 31) ab = 0;
        unsigned m = __ballot_sync(0xffffffffu, v >= kr);
        if (m != 0u) {
            int L = 31 - __clz(m);
            if (t == L) {
                unsigned cum = ab;
                int bin = 0; unsigned krn = 1;
                for (int g = 7; g >= 0; --g) {
                    int gi = L * 8 + g;
                    unsigned pg = part[gi];
                    if (cum + pg >= kr) {
                        for (int b = 7; b >= 0; --b) {
                            int bi = gi * 8 + b;
                            unsigned hb = hget(h32, (unsigned)bi);
                            if (cum + hb >= kr) { bin = bi; krn = kr - cum; break; }
                            cum += hb;
                        }
                        break;
                    }
                    cum += pg;
                }
                *sh_bin = (unsigned)bin;
                *sh_kr  = krn;
            }
        }
    }
    __syncthreads();
}

// ---------------------------------------------------------------------------
// Kernel 2: one CTA per row.
//  load   : row -> monotonic keys in smem; SAMPLED (first 2048 elems) packed
//           atomic hist on top 11 bits
//  locate : sampled select -> approx threshold bin B1s; bracket [B1s-2,B1s+2]
//  collect: exact count(bin > hi) via register adds + gather bracket keys
//  exact  : 3-level radix select on the <=1024-entry list (exact threshold)
//  fallbk : full-sweep packed-hist radix select if bracket missed (rare)
//  output : vectorized threshold write + bit-interleaved positivity mask
// ---------------------------------------------------------------------------
__global__ __launch_bounds__(256)
void topk_kernel(const float* __restrict__ in, float* __restrict__ out) {
    extern __shared__ unsigned smem[];
    unsigned* keys = smem;            // 8192 words
    unsigned* h32  = smem + 8192;     // 1024 words (2048 packed u16 bins)
    unsigned* list = smem + 9216;     // 1024 words
    unsigned* part = smem + 10240;    // 256 words
    __shared__ unsigned sh_bin, sh_kr, sh_cnt, sh_above;

    const int t = threadIdx.x;
    const int lane = t & 31, w = t >> 5;
    const int row = blockIdx.x;

    for (int i = t; i < 1024; i += 256) h32[i] = 0;
    if (t == 0) { sh_cnt = 0; sh_above = 0; }
    __syncthreads();

    // ---- load pass: read row, form keys; hist only iterations 0..1 (2048 samples)
    const float4* __restrict__ rowp =
        reinterpret_cast<const float4*>(in) + (size_t)row * (F_COLS / 4);
    const float4* __restrict__ bp = reinterpret_cast<const float4*>(g_boost);
#pragma unroll
    for (int it = 0; it < 8; ++it) {
        int i4 = it * 256 + t;
        float4 v = rowp[i4];
        float4 b = bp[i4];
        float f0 = v.x * b.x, f1 = v.y * b.y, f2 = v.z * b.z, f3 = v.w * b.w;
        unsigned u0 = __float_as_uint(f0), u1 = __float_as_uint(f1);
        unsigned u2 = __float_as_uint(f2), u3 = __float_as_uint(f3);
        unsigned k0 = (u0 & 0x80000000u) ? ~u0 : (u0 | 0x80000000u);
        unsigned k1 = (u1 & 0x80000000u) ? ~u1 : (u1 | 0x80000000u);
        unsigned k2 = (u2 & 0x80000000u) ? ~u2 : (u2 | 0x80000000u);
        unsigned k3 = (u3 & 0x80000000u) ? ~u3 : (u3 | 0x80000000u);
        reinterpret_cast<uint4*>(keys)[i4] = make_uint4(k0, k1, k2, k3);
        if (it < 2) {
            hinc(h32, k0 >> 21);
            hinc(h32, k1 >> 21);
            hinc(h32, k2 >> 21);
            hinc(h32, k3 >> 21);
        }
    }
    __syncthreads();

    // ---- sampled select: approximate threshold bin
    select_bin_p(h32, part, KR_SAMP, &sh_bin, &sh_kr);
    const int B1s = (int)sh_bin;
    const int lo = B1s > 2 ? B1s - 2 : 0;
    const int hi = B1s < 2045 ? B1s + 2 : 2047;
    __syncthreads();   // part fully consumed before reuse below

    // ---- collect sweep: exact above-count + bracket candidate list
    unsigned above = 0;
#pragma unroll
    for (int it = 0; it < 8; ++it) {
        uint4 kk = reinterpret_cast<const uint4*>(keys)[it * 256 + t];
        unsigned b0 = kk.x >> 21, b1 = kk.y >> 21, b2 = kk.z >> 21, b3 = kk.w >> 21;
        above += (b0 > (unsigned)hi) + (b1 > (unsigned)hi) +
                 (b2 > (unsigned)hi) + (b3 > (unsigned)hi);
        if (b0 >= (unsigned)lo && b0 <= (unsigned)hi) {
            unsigned p = atomicAdd(&sh_cnt, 1u); if (p < 1024u) list[p] = kk.x;
        }
        if (b1 >= (unsigned)lo && b1 <= (unsigned)hi) {
            unsigned p = atomicAdd(&sh_cnt, 1u); if (p < 1024u) list[p] = kk.y;
        }
        if (b2 >= (unsigned)lo && b2 <= (unsigned)hi) {
            unsigned p = atomicAdd(&sh_cnt, 1u); if (p < 1024u) list[p] = kk.z;
        }
        if (b3 >= (unsigned)lo && b3 <= (unsigned)hi) {
            unsigned p = atomicAdd(&sh_cnt, 1u); if (p < 1024u) list[p] = kk.w;
        }
    }
    part[t] = above;
    __syncthreads();
    if (t < 32) {
        unsigned s = 0;
#pragma unroll
        for (int i = 0; i < 8; ++i) s += part[t * 8 + i];
#pragma unroll
        for (int off = 16; off > 0; off >>= 1)
            s += __shfl_down_sync(0xffffffffu, s, off);
        if (t == 0) sh_above = s;
    }
    __syncthreads();
    const unsigned m   = sh_cnt;
    const unsigned abv = sh_above;

    unsigned T;
    const bool listok = (m <= 1024u) && (K_SEL > abv) && (K_SEL - abv <= m);
    if (listok) {
        const unsigned kr1 = K_SEL - abv;     // 1 <= kr1 <= m by guard
        // ---- level A: top 11 bits over list
        __syncthreads();
        for (int i = t; i < 1024; i += 256) h32[i] = 0;
        __syncthreads();
        for (unsigned i = t; i < m; i += 256) hinc(h32, list[i] >> 21);
        __syncthreads();
        select_bin_p(h32, part, kr1, &sh_bin, &sh_kr);
        const unsigned bA = sh_bin, krB = sh_kr;

        // ---- level B: bits 20..10 over list matching bA
        __syncthreads();
        for (int i = t; i < 1024; i += 256) h32[i] = 0;
        __syncthreads();
        for (unsigned i = t; i < m; i += 256) {
            unsigned k = list[i];
            if ((k >> 21) == bA) hinc(h32, (k >> 10) & 0x7FFu);
        }
        __syncthreads();
        select_bin_p(h32, part, krB, &sh_bin, &sh_kr);
        const unsigned pref22 = (bA << 11) | sh_bin;
        const unsigned krC = sh_kr;

        // ---- level C: bits 9..0 over list matching pref22
        __syncthreads();
        for (int i = t; i < 1024; i += 256) h32[i] = 0;
        __syncthreads();
        for (unsigned i = t; i < m; i += 256) {
            unsigned k = list[i];
            if ((k >> 10) == pref22) hinc(h32, k & 0x3FFu);
        }
        __syncthreads();
        select_bin_p(h32, part, krC, &sh_bin, &sh_kr);
        T = (pref22 << 10) | sh_bin;
    } else {
        // ---- fallback: exact full-sweep 3-pass radix (any input)
        __syncthreads();
        for (int i = t; i < 1024; i += 256) h32[i] = 0;
        __syncthreads();
#pragma unroll
        for (int it = 0; it < 8; ++it) {
            uint4 kk = reinterpret_cast<const uint4*>(keys)[it * 256 + t];
            hinc(h32, kk.x >> 21); hinc(h32, kk.y >> 21);
            hinc(h32, kk.z >> 21); hinc(h32, kk.w >> 21);
        }
        __syncthreads();
        select_bin_p(h32, part, K_SEL, &sh_bin, &sh_kr);
        const unsigned B1 = sh_bin, kr2 = sh_kr;

        __syncthreads();
        for (int i = t; i < 1024; i += 256) h32[i] = 0;
        __syncthreads();
#pragma unroll
        for (int it = 0; it < 8; ++it) {
            uint4 kk = reinterpret_cast<const uint4*>(keys)[it * 256 + t];
            if ((kk.x >> 21) == B1) hinc(h32, (kk.x >> 10) & 0x7FFu);
            if ((kk.y >> 21) == B1) hinc(h32, (kk.y >> 10) & 0x7FFu);
            if ((kk.z >> 21) == B1) hinc(h32, (kk.z >> 10) & 0x7FFu);
            if ((kk.w >> 21) == B1) hinc(h32, (kk.w >> 10) & 0x7FFu);
        }
        __syncthreads();
        select_bin_p(h32, part, kr2, &sh_bin, &sh_kr);
        const unsigned pref22 = (B1 << 11) | sh_bin;
        const unsigned kr3 = sh_kr;

        __syncthreads();
        for (int i = t; i < 1024; i += 256) h32[i] = 0;
        __syncthreads();
#pragma unroll
        for (int it = 0; it < 8; ++it) {
            uint4 kk = reinterpret_cast<const uint4*>(keys)[it * 256 + t];
            if ((kk.x >> 10) == pref22) hinc(h32, kk.x & 0x3FFu);
            if ((kk.y >> 10) == pref22) hinc(h32, kk.y & 0x3FFu);
            if ((kk.z >> 10) == pref22) hinc(h32, kk.z & 0x3FFu);
            if ((kk.w >> 10) == pref22) hinc(h32, kk.w & 0x3FFu);
        }
        __syncthreads();
        select_bin_p(h32, part, kr3, &sh_bin, &sh_kr);
        T = (pref22 << 10) | sh_bin;
    }

    // ---- output pass (vectorized): threshold, reconstruct, interleaved mask
    float4* __restrict__ orow =
        reinterpret_cast<float4*>(out) + (size_t)row * (F_COLS / 4);
    const float4* __restrict__ rbp = reinterpret_cast<const float4*>(g_rboost);
#pragma unroll
    for (int it = 0; it < 8; ++it) {
        int i4 = it * 256 + t;
        uint4 kk = reinterpret_cast<const uint4*>(keys)[i4];
        float4 rb = rbp[i4];
        bool c0 = kk.x >= T, c1 = kk.y >= T, c2 = kk.z >= T, c3 = kk.w >= T;
        unsigned b0 = (kk.x & 0x80000000u) ? (kk.x & 0x7FFFFFFFu) : ~kk.x;
        unsigned b1 = (kk.y & 0x80000000u) ? (kk.y & 0x7FFFFFFFu) : ~kk.y;
        unsigned b2 = (kk.z & 0x80000000u) ? (kk.z & 0x7FFFFFFFu) : ~kk.z;
        unsigned b3 = (kk.w & 0x80000000u) ? (kk.w & 0x7FFFFFFFu) : ~kk.w;
        float4 o;
        o.x = c0 ? __uint_as_float(b0) * rb.x : 0.0f;
        o.y = c1 ? __uint_as_float(b1) * rb.y : 0.0f;
        o.z = c2 ? __uint_as_float(b2) * rb.z : 0.0f;
        o.w = c3 ? __uint_as_float(b3) * rb.w : 0.0f;
        orow[i4] = o;
        unsigned m0 = __ballot_sync(0xffffffffu, c0 && kk.x > 0x80000000u);
        unsigned m1 = __ballot_sync(0xffffffffu, c1 && kk.y > 0x80000000u);
        unsigned m2 = __ballot_sync(0xffffffffu, c2 && kk.z > 0x80000000u);
        unsigned m3 = __ballot_sync(0xffffffffu, c3 && kk.w > 0x80000000u);
        int group = it * 8 + w;          // 128-column group, 0..63
        size_t base = (size_t)(group * 4) * N_ROWS + row;
        if (lane == 0) g_mask[base]              = m0;
        if (lane == 1) g_mask[base + N_ROWS]     = m1;
        if (lane == 2) g_mask[base + 2 * N_ROWS] = m2;
        if (lane == 3) g_mask[base + 3 * N_ROWS] = m3;
    }
}

// ---------------------------------------------------------------------------
// Kernel 3: column counts via ballot bit-transpose, then EMA.
// Block wc owns mask word-column wc; bit i <-> column (wc>>2)*128+4*i+(wc&3).
// ---------------------------------------------------------------------------
__global__ __launch_bounds__(256)
void dc_kernel(const float* __restrict__ dc, float* __restrict__ dcout) {
    __shared__ unsigned s[256];
    const int t = threadIdx.x, lane = t & 31, wi = t >> 5;
    const int wc = blockIdx.x;
    const unsigned* __restrict__ mp = g_mask + (size_t)wc * N_ROWS;

    unsigned cnt = 0;
    const int r0 = wi * 1024;
    for (int g = 0; g < 32; ++g) {
        unsigned word = mp[r0 + g * 32 + lane];
#pragma unroll
        for (int i = 0; i < 32; ++i) {
            unsigned bal = __ballot_sync(0xffffffffu, (word >> i) & 1u);
            if (lane == i) cnt += __popc(bal);
        }
    }
    s[t] = cnt;
    __syncthreads();
    if (t < 32) {
        unsigned tot = 0;
#pragma unroll
        for (int i = 0; i < 8; ++i) tot += s[i * 32 + t];
        int col = (wc >> 2) * 128 + 4 * t + (wc & 3);
        dcout[col] = 0.9f * dc[col] + 0.1f * (float)tot;
    }
}

// ---------------------------------------------------------------------------
extern "C" void kernel_launch(void* const* d_in, const int* in_sizes, int n_in,
                              void* d_out, int out_size) {
    const float* inputs = (const float*)d_in[0];
    const float* dc     = (const float*)d_in[1];
    if (n_in >= 2 && in_sizes[0] < in_sizes[1]) {
        const float* tmp = inputs; inputs = dc; dc = tmp;
    }
    float* out = (float*)d_out;

    boost_kernel<<<(F_COLS + 255) / 256, 256>>>(dc);

    const int smem_bytes = (8192 + 1024 + 1024 + 256) * 4;   // 41984 B, 5 CTAs/SM
    topk_kernel<<<N_ROWS, 256, smem_bytes>>>(inputs, out);

    if (out_size >= (int)((size_t)N_ROWS * F_COLS + F_COLS)) {
        float* dcout = out + (size_t)N_ROWS * F_COLS;
        dc_kernel<<<256, 256>>>(dc, dcout);
    }
}

// round 12
// speedup vs baseline: 1.0849x; 1.0849x over previous
#include <cuda_runtime.h>
#include <cstdint>

#define N_ROWS 8192
#define F_COLS 8192
#define K_SEL  2867u

// Scratch (static __device__ arrays — allocation-free per harness rules)
__device__ __align__(16) float g_boost[F_COLS];
__device__ __align__(16) float g_rboost[F_COLS];
// Bit-interleaved positivity mask: word index wc in [0,256):
//   group = wc>>2, b = wc&3; bit i of word <-> column group*128 + 4*i + b
// stored transposed: g_mask[wc * N_ROWS + row]
__device__ unsigned g_mask[256 * N_ROWS];

// ---------------------------------------------------------------------------
// Kernel 1: boost = exp(BETA*(target - duty_cycle)) and its reciprocal
// ---------------------------------------------------------------------------
__global__ void boost_kernel(const float* __restrict__ dc) {
    int j = blockIdx.x * blockDim.x + threadIdx.x;
    if (j < F_COLS) {
        const float target = 2867.0f / 8192.0f;   // exact dyadic
        float b = expf(1.5f * (target - dc[j]));
        g_boost[j]  = b;
        g_rboost[j] = 1.0f / b;
    }
}

// ---------------------------------------------------------------------------
// Packed-u16 histogram: 2048 bins in 1024 u32 words (counts <= 8192, no carry)
// ---------------------------------------------------------------------------
__device__ __forceinline__ void hinc(unsigned* __restrict__ h32, unsigned bin) {
    atomicAdd(&h32[bin >> 1], (bin & 1u) ? 0x10000u : 1u);
}
__device__ __forceinline__ unsigned hget(const unsigned* __restrict__ h32,
                                         unsigned bin) {
    return (h32[bin >> 1] >> ((bin & 1u) * 16u)) & 0xFFFFu;
}

// Monotonic order-preserving key for float bits u.
__device__ __forceinline__ unsigned fkey(unsigned u) {
    return u ^ (((unsigned)((int)u >> 31)) | 0x80000000u);
}

// ---------------------------------------------------------------------------
// Radix-select over a packed 2048-bin histogram: find bin B with
//   count(bins > B) < kr <= count(bins >= B);  writes B and residual rank.
// Defined for all inputs (kr > total -> bin 0, rank 1).
// ---------------------------------------------------------------------------
__device__ __forceinline__ void select_bin_p(const unsigned* __restrict__ h32,
                                             unsigned* __restrict__ part,
                                             unsigned kr,
                                             volatile unsigned* sh_bin,
                                             volatile unsigned* sh_kr) {
    int t = threadIdx.x;
    if (t == 0) { *sh_bin = 0; *sh_kr = 1; }
    unsigned s = 0;
#pragma unroll
    for (int i = 0; i < 4; ++i) {
        unsigned wv = h32[t * 4 + i];
        s += (wv & 0xFFFFu) + (wv >> 16);
    }
    part[t] = s;
    __syncthreads();

    if (t < 32) {
        unsigned c = 0;
#pragma unroll
        for (int i = 0; i < 8; ++i) c += part[t * 8 + i];
        unsigned v = c;
#pragma unroll
        for (int off = 1; off < 32; off <<= 1) {
            unsigned u = __shfl_down_sync(0xffffffffu, v, off);
            if (t + off < 32) v += u;
        }
        unsigned ab = __shfl_down_sync(0xffffffffu, v, 1);
        if (t == 31) ab = 0;
        unsigned m = __ballot_sync(0xffffffffu, v >= kr);
        if (m != 0u) {
            int L = 31 - __clz(m);
            if (t == L) {
                unsigned cum = ab;
                int bin = 0; unsigned krn = 1;
                for (int g = 7; g >= 0; --g) {
                    int gi = L * 8 + g;
                    unsigned pg = part[gi];
                    if (cum + pg >= kr) {
                        for (int b = 7; b >= 0; --b) {
                            int bi = gi * 8 + b;
                            unsigned hb = hget(h32, (unsigned)bi);
                            if (cum + hb >= kr) { bin = bi; krn = kr - cum; break; }
                            cum += hb;
                        }
                        break;
                    }
                    cum += pg;
                }
                *sh_bin = (unsigned)bin;
                *sh_kr  = krn;
            }
        }
    }
    __syncthreads();
}

// ---------------------------------------------------------------------------
// Kernel 2: one CTA per row.
//  pass 1 : load row -> keys in smem, packed hist on bits 31..21
//  pass 2 : hist of bits 20..10 over threshold-bin keys, FUSED with
//           collection of those keys into a compact list (~190 expected)
//  level 3: bits 9..0 over the list (1 short iteration); overflow -> full sweep
//  output : vectorized threshold write + bit-interleaved positivity mask
// ---------------------------------------------------------------------------
__global__ __launch_bounds__(256)
void topk_kernel(const float* __restrict__ in, float* __restrict__ out) {
    extern __shared__ unsigned smem[];
    unsigned* keys = smem;            // 8192 words
    unsigned* h32  = smem + 8192;     // 1024 words (2048 packed u16 bins)
    unsigned* list = smem + 9216;     // 1024 words
    unsigned* part = smem + 10240;    // 256 words
    __shared__ unsigned sh_bin, sh_kr, sh_cnt;

    const int t = threadIdx.x;
    const int lane = t & 31, w = t >> 5;
    const int row = blockIdx.x;

    reinterpret_cast<uint4*>(h32)[t] = make_uint4(0, 0, 0, 0);
    if (t == 0) sh_cnt = 0;
    __syncthreads();

    // ---- pass 1: read row, form keys, packed hist top 11 bits
    const float4* __restrict__ rowp =
        reinterpret_cast<const float4*>(in) + (size_t)row * (F_COLS / 4);
    const float4* __restrict__ bp = reinterpret_cast<const float4*>(g_boost);
#pragma unroll
    for (int it = 0; it < 8; ++it) {
        int i4 = it * 256 + t;
        float4 v = rowp[i4];
        float4 b = bp[i4];
        unsigned k0 = fkey(__float_as_uint(v.x * b.x));
        unsigned k1 = fkey(__float_as_uint(v.y * b.y));
        unsigned k2 = fkey(__float_as_uint(v.z * b.z));
        unsigned k3 = fkey(__float_as_uint(v.w * b.w));
        reinterpret_cast<uint4*>(keys)[i4] = make_uint4(k0, k1, k2, k3);
        hinc(h32, k0 >> 21);
        hinc(h32, k1 >> 21);
        hinc(h32, k2 >> 21);
        hinc(h32, k3 >> 21);
    }
    __syncthreads();

    select_bin_p(h32, part, K_SEL, &sh_bin, &sh_kr);
    const unsigned B1 = sh_bin, kr2 = sh_kr;

    // ---- pass 2 (fused with collect): bits 20..10 over keys matching B1
    reinterpret_cast<uint4*>(h32)[t] = make_uint4(0, 0, 0, 0);
    __syncthreads();
#pragma unroll
    for (int it = 0; it < 8; ++it) {
        uint4 kk = reinterpret_cast<const uint4*>(keys)[it * 256 + t];
        if ((kk.x >> 21) == B1) {
            hinc(h32, (kk.x >> 10) & 0x7FFu);
            unsigned p = atomicAdd(&sh_cnt, 1u); if (p < 1024u) list[p] = kk.x;
        }
        if ((kk.y >> 21) == B1) {
            hinc(h32, (kk.y >> 10) & 0x7FFu);
            unsigned p = atomicAdd(&sh_cnt, 1u); if (p < 1024u) list[p] = kk.y;
        }
        if ((kk.z >> 21) == B1) {
            hinc(h32, (kk.z >> 10) & 0x7FFu);
            unsigned p = atomicAdd(&sh_cnt, 1u); if (p < 1024u) list[p] = kk.z;
        }
        if ((kk.w >> 21) == B1) {
            hinc(h32, (kk.w >> 10) & 0x7FFu);
            unsigned p = atomicAdd(&sh_cnt, 1u); if (p < 1024u) list[p] = kk.w;
        }
    }
    __syncthreads();
    select_bin_p(h32, part, kr2, &sh_bin, &sh_kr);
    const unsigned pref22 = (B1 << 11) | sh_bin;
    const unsigned kr3 = sh_kr;
    const unsigned m = sh_cnt;

    // ---- level 3: bits 9..0
    reinterpret_cast<uint4*>(h32)[t] = make_uint4(0, 0, 0, 0);
    __syncthreads();
    if (m <= 1024u) {
        // list holds ALL threshold-bin candidates -> exact
        for (unsigned i = t; i < m; i += 256) {
            unsigned k = list[i];
            if ((k >> 10) == pref22) hinc(h32, k & 0x3FFu);
        }
    } else {
        // fallback: full sweep (adversarial inputs only)
#pragma unroll
        for (int it = 0; it < 8; ++it) {
            uint4 kk = reinterpret_cast<const uint4*>(keys)[it * 256 + t];
            if ((kk.x >> 10) == pref22) hinc(h32, kk.x & 0x3FFu);
            if ((kk.y >> 10) == pref22) hinc(h32, kk.y & 0x3FFu);
            if ((kk.z >> 10) == pref22) hinc(h32, kk.z & 0x3FFu);
            if ((kk.w >> 10) == pref22) hinc(h32, kk.w & 0x3FFu);
        }
    }
    __syncthreads();
    select_bin_p(h32, part, kr3, &sh_bin, &sh_kr);
    const unsigned T = (pref22 << 10) | sh_bin;    // k-th largest key

    // ---- output pass (vectorized): threshold, reconstruct, interleaved mask
    float4* __restrict__ orow =
        reinterpret_cast<float4*>(out) + (size_t)row * (F_COLS / 4);
    const float4* __restrict__ rbp = reinterpret_cast<const float4*>(g_rboost);
#pragma unroll
    for (int it = 0; it < 8; ++it) {
        int i4 = it * 256 + t;
        uint4 kk = reinterpret_cast<const uint4*>(keys)[i4];
        float4 rb = rbp[i4];
        bool c0 = kk.x >= T, c1 = kk.y >= T, c2 = kk.z >= T, c3 = kk.w >= T;
        // inverse key: bits = k ^ (0x80000000 | ~((int)k>>31))  (SHF+LOP3)
        unsigned b0 = kk.x ^ (0x80000000u | ~(unsigned)((int)kk.x >> 31));
        unsigned b1 = kk.y ^ (0x80000000u | ~(unsigned)((int)kk.y >> 31));
        unsigned b2 = kk.z ^ (0x80000000u | ~(unsigned)((int)kk.z >> 31));
        unsigned b3 = kk.w ^ (0x80000000u | ~(unsigned)((int)kk.w >> 31));
        float4 o;
        o.x = c0 ? __uint_as_float(b0) * rb.x : 0.0f;
        o.y = c1 ? __uint_as_float(b1) * rb.y : 0.0f;
        o.z = c2 ? __uint_as_float(b2) * rb.z : 0.0f;
        o.w = c3 ? __uint_as_float(b3) * rb.w : 0.0f;
        orow[i4] = o;
        unsigned m0 = __ballot_sync(0xffffffffu, c0 && kk.x > 0x80000000u);
        unsigned m1 = __ballot_sync(0xffffffffu, c1 && kk.y > 0x80000000u);
        unsigned m2 = __ballot_sync(0xffffffffu, c2 && kk.z > 0x80000000u);
        unsigned m3 = __ballot_sync(0xffffffffu, c3 && kk.w > 0x80000000u);
        int group = it * 8 + w;          // 128-column group, 0..63
        size_t base = (size_t)(group * 4) * N_ROWS + row;
        if (lane == 0) g_mask[base]              = m0;
        if (lane == 1) g_mask[base + N_ROWS]     = m1;
        if (lane == 2) g_mask[base + 2 * N_ROWS] = m2;
        if (lane == 3) g_mask[base + 3 * N_ROWS] = m3;
    }
}

// ---------------------------------------------------------------------------
// Kernel 3: column counts via ballot bit-transpose, then EMA.
// Block wc owns mask word-column wc; bit i <-> column (wc>>2)*128+4*i+(wc&3).
// ---------------------------------------------------------------------------
__global__ __launch_bounds__(256)
void dc_kernel(const float* __restrict__ dc, float* __restrict__ dcout) {
    __shared__ unsigned s[256];
    const int t = threadIdx.x, lane = t & 31, wi = t >> 5;
    const int wc = blockIdx.x;
    const unsigned* __restrict__ mp = g_mask + (size_t)wc * N_ROWS;

    unsigned cnt = 0;
    const int r0 = wi * 1024;
    for (int g = 0; g < 32; ++g) {
        unsigned word = mp[r0 + g * 32 + lane];
#pragma unroll
        for (int i = 0; i < 32; ++i) {
            unsigned bal = __ballot_sync(0xffffffffu, (word >> i) & 1u);
            if (lane == i) cnt += __popc(bal);
        }
    }
    s[t] = cnt;
    __syncthreads();
    if (t < 32) {
        unsigned tot = 0;
#pragma unroll
        for (int i = 0; i < 8; ++i) tot += s[i * 32 + t];
        int col = (wc >> 2) * 128 + 4 * t + (wc & 3);
        dcout[col] = 0.9f * dc[col] + 0.1f * (float)tot;
    }
}

// ---------------------------------------------------------------------------
extern "C" void kernel_launch(void* const* d_in, const int* in_sizes, int n_in,
                              void* d_out, int out_size) {
    const float* inputs = (const float*)d_in[0];
    const float* dc     = (const float*)d_in[1];
    if (n_in >= 2 && in_sizes[0] < in_sizes[1]) {
        const float* tmp = inputs; inputs = dc; dc = tmp;
    }
    float* out = (float*)d_out;

    boost_kernel<<<(F_COLS + 255) / 256, 256>>>(dc);

    const int smem_bytes = (8192 + 1024 + 1024 + 256) * 4;   // 41984 B, 5 CTAs/SM
    topk_kernel<<<N_ROWS, 256, smem_bytes>>>(inputs, out);

    if (out_size >= (int)((size_t)N_ROWS * F_COLS + F_COLS)) {
        float* dcout = out + (size_t)N_ROWS * F_COLS;
        dc_kernel<<<256, 256>>>(dc, dcout);
    }
}

// round 13
// speedup vs baseline: 1.1645x; 1.0734x over previous
#include <cuda_runtime.h>
#include <cstdint>

#define N_ROWS 8192
#define F_COLS 8192
#define K_SEL  2867u

// Scratch (static __device__ arrays — allocation-free per harness rules)
__device__ __align__(16) float g_boost[F_COLS];
__device__ __align__(16) float g_rboost[F_COLS];
// Bit-interleaved positivity mask: word index wc in [0,256):
//   group = wc>>2, b = wc&3; bit i of word <-> column group*128 + 4*i + b
// stored transposed: g_mask[wc * N_ROWS + row]
__device__ unsigned g_mask[256 * N_ROWS];

// ---------------------------------------------------------------------------
// Kernel 1: boost = exp(BETA*(target - duty_cycle)) and its reciprocal
// ---------------------------------------------------------------------------
__global__ void boost_kernel(const float* __restrict__ dc) {
    int j = blockIdx.x * blockDim.x + threadIdx.x;
    if (j < F_COLS) {
        const float target = 2867.0f / 8192.0f;   // exact dyadic
        float b = expf(1.5f * (target - dc[j]));
        g_boost[j]  = b;
        g_rboost[j] = 1.0f / b;
    }
}

// Monotonic order-preserving key for float bits u.
__device__ __forceinline__ unsigned fkey(unsigned u) {
    return u ^ (((unsigned)((int)u >> 31)) | 0x80000000u);
}

// ---------------------------------------------------------------------------
// Radix-select over an UNPACKED 2048-bin u32 histogram: find bin B with
//   count(bins > B) < kr <= count(bins >= B);  writes B and residual rank.
// Defined for all inputs (kr > total -> bin 0, rank 1).
// ---------------------------------------------------------------------------
__device__ __forceinline__ void select_bin(const unsigned* __restrict__ hist,
                                           unsigned* __restrict__ part,
                                           unsigned kr,
                                           volatile unsigned* sh_bin,
                                           volatile unsigned* sh_kr) {
    int t = threadIdx.x;
    if (t == 0) { *sh_bin = 0; *sh_kr = 1; }
    unsigned s = 0;
#pragma unroll
    for (int i = 0; i < 8; ++i) s += hist[t * 8 + i];
    part[t] = s;
    __syncthreads();

    if (t < 32) {
        unsigned c = 0;
#pragma unroll
        for (int i = 0; i < 8; ++i) c += part[t * 8 + i];
        unsigned v = c;
#pragma unroll
        for (int off = 1; off < 32; off <<= 1) {
            unsigned u = __shfl_down_sync(0xffffffffu, v, off);
            if (t + off < 32) v += u;
        }
        unsigned ab = __shfl_down_sync(0xffffffffu, v, 1);
        if (t == 31) ab = 0;
        unsigned m = __ballot_sync(0xffffffffu, v >= kr);
        if (m != 0u) {
            int L = 31 - __clz(m);
            if (t == L) {
                unsigned cum = ab;
                int bin = 0; unsigned krn = 1;
                for (int g = 7; g >= 0; --g) {
                    int gi = L * 8 + g;
                    unsigned pg = part[gi];
                    if (cum + pg >= kr) {
                        for (int b = 7; b >= 0; --b) {
                            int bi = gi * 8 + b;
                            unsigned hb = hist[bi];
                            if (cum + hb >= kr) { bin = bi; krn = kr - cum; break; }
                            cum += hb;
                        }
                        break;
                    }
                    cum += pg;
                }
                *sh_bin = (unsigned)bin;
                *sh_kr  = krn;
            }
        }
    }
    __syncthreads();
}

// ---------------------------------------------------------------------------
// Kernel 2: one CTA per row.
//  pass 1 : load row -> keys in smem, 2048-word atomic hist on bits 31..21
//  pass 2 : hist of bits 20..10 over threshold-bin keys, FUSED with
//           collection of those keys into a 512-entry list (~190 expected)
//  level 3: bits 9..0 over the list (~1 short iteration); overflow -> sweep
//  output : vectorized threshold write + bit-interleaved positivity mask
// ---------------------------------------------------------------------------
__global__ __launch_bounds__(256)
void topk_kernel(const float* __restrict__ in, float* __restrict__ out) {
    extern __shared__ unsigned smem[];
    unsigned* keys = smem;            // 8192 words
    unsigned* hist = smem + 8192;     // 2048 words (unpacked u32 bins)
    unsigned* list = smem + 10240;    // 512 words
    unsigned* part = smem + 10752;    // 256 words
    __shared__ unsigned sh_bin, sh_kr, sh_cnt;

    const int t = threadIdx.x;
    const int lane = t & 31, w = t >> 5;
    const int row = blockIdx.x;

    reinterpret_cast<uint4*>(hist)[t]       = make_uint4(0, 0, 0, 0);
    reinterpret_cast<uint4*>(hist)[t + 256] = make_uint4(0, 0, 0, 0);
    if (t == 0) sh_cnt = 0;
    __syncthreads();

    // ---- pass 1: read row, form keys, hist top 11 bits (unpacked)
    const float4* __restrict__ rowp =
        reinterpret_cast<const float4*>(in) + (size_t)row * (F_COLS / 4);
    const float4* __restrict__ bp = reinterpret_cast<const float4*>(g_boost);
#pragma unroll
    for (int it = 0; it < 8; ++it) {
        int i4 = it * 256 + t;
        float4 v = rowp[i4];
        float4 b = bp[i4];
        unsigned k0 = fkey(__float_as_uint(v.x * b.x));
        unsigned k1 = fkey(__float_as_uint(v.y * b.y));
        unsigned k2 = fkey(__float_as_uint(v.z * b.z));
        unsigned k3 = fkey(__float_as_uint(v.w * b.w));
        reinterpret_cast<uint4*>(keys)[i4] = make_uint4(k0, k1, k2, k3);
        atomicAdd(&hist[k0 >> 21], 1u);
        atomicAdd(&hist[k1 >> 21], 1u);
        atomicAdd(&hist[k2 >> 21], 1u);
        atomicAdd(&hist[k3 >> 21], 1u);
    }
    __syncthreads();

    select_bin(hist, part, K_SEL, &sh_bin, &sh_kr);
    const unsigned B1 = sh_bin, kr2 = sh_kr;

    // ---- pass 2 (fused with collect): bits 20..10 over keys matching B1
    reinterpret_cast<uint4*>(hist)[t]       = make_uint4(0, 0, 0, 0);
    reinterpret_cast<uint4*>(hist)[t + 256] = make_uint4(0, 0, 0, 0);
    __syncthreads();
#pragma unroll
    for (int it = 0; it < 8; ++it) {
        uint4 kk = reinterpret_cast<const uint4*>(keys)[it * 256 + t];
        if ((kk.x >> 21) == B1) {
            atomicAdd(&hist[(kk.x >> 10) & 0x7FFu], 1u);
            unsigned p = atomicAdd(&sh_cnt, 1u); if (p < 512u) list[p] = kk.x;
        }
        if ((kk.y >> 21) == B1) {
            atomicAdd(&hist[(kk.y >> 10) & 0x7FFu], 1u);
            unsigned p = atomicAdd(&sh_cnt, 1u); if (p < 512u) list[p] = kk.y;
        }
        if ((kk.z >> 21) == B1) {
            atomicAdd(&hist[(kk.z >> 10) & 0x7FFu], 1u);
            unsigned p = atomicAdd(&sh_cnt, 1u); if (p < 512u) list[p] = kk.z;
        }
        if ((kk.w >> 21) == B1) {
            atomicAdd(&hist[(kk.w >> 10) & 0x7FFu], 1u);
            unsigned p = atomicAdd(&sh_cnt, 1u); if (p < 512u) list[p] = kk.w;
        }
    }
    __syncthreads();
    select_bin(hist, part, kr2, &sh_bin, &sh_kr);
    const unsigned pref22 = (B1 << 11) | sh_bin;
    const unsigned kr3 = sh_kr;
    const unsigned m = sh_cnt;

    // ---- level 3: bits 9..0 (1024 bins live; upper 1024 words stay 0)
    reinterpret_cast<uint4*>(hist)[t]       = make_uint4(0, 0, 0, 0);
    reinterpret_cast<uint4*>(hist)[t + 256] = make_uint4(0, 0, 0, 0);
    __syncthreads();
    if (m <= 512u) {
        // list holds ALL threshold-bin candidates -> exact
        for (unsigned i = t; i < m; i += 256) {
            unsigned k = list[i];
            if ((k >> 10) == pref22) atomicAdd(&hist[k & 0x3FFu], 1u);
        }
    } else {
        // fallback: full sweep (adversarial inputs only)
#pragma unroll
        for (int it = 0; it < 8; ++it) {
            uint4 kk = reinterpret_cast<const uint4*>(keys)[it * 256 + t];
            if ((kk.x >> 10) == pref22) atomicAdd(&hist[kk.x & 0x3FFu], 1u);
            if ((kk.y >> 10) == pref22) atomicAdd(&hist[kk.y & 0x3FFu], 1u);
            if ((kk.z >> 10) == pref22) atomicAdd(&hist[kk.z & 0x3FFu], 1u);
            if ((kk.w >> 10) == pref22) atomicAdd(&hist[kk.w & 0x3FFu], 1u);
        }
    }
    __syncthreads();
    select_bin(hist, part, kr3, &sh_bin, &sh_kr);
    const unsigned T = (pref22 << 10) | sh_bin;    // k-th largest key

    // ---- output pass (vectorized): threshold, reconstruct, interleaved mask
    float4* __restrict__ orow =
        reinterpret_cast<float4*>(out) + (size_t)row * (F_COLS / 4);
    const float4* __restrict__ rbp = reinterpret_cast<const float4*>(g_rboost);
#pragma unroll
    for (int it = 0; it < 8; ++it) {
        int i4 = it * 256 + t;
        uint4 kk = reinterpret_cast<const uint4*>(keys)[i4];
        float4 rb = rbp[i4];
        bool c0 = kk.x >= T, c1 = kk.y >= T, c2 = kk.z >= T, c3 = kk.w >= T;
        // inverse key: bits = k ^ (0x80000000 | ~((int)k>>31))
        unsigned b0 = kk.x ^ (0x80000000u | ~(unsigned)((int)kk.x >> 31));
        unsigned b1 = kk.y ^ (0x80000000u | ~(unsigned)((int)kk.y >> 31));
        unsigned b2 = kk.z ^ (0x80000000u | ~(unsigned)((int)kk.z >> 31));
        unsigned b3 = kk.w ^ (0x80000000u | ~(unsigned)((int)kk.w >> 31));
        float4 o;
        o.x = c0 ? __uint_as_float(b0) * rb.x : 0.0f;
        o.y = c1 ? __uint_as_float(b1) * rb.y : 0.0f;
        o.z = c2 ? __uint_as_float(b2) * rb.z : 0.0f;
        o.w = c3 ? __uint_as_float(b3) * rb.w : 0.0f;
        orow[i4] = o;
        unsigned m0 = __ballot_sync(0xffffffffu, c0 && kk.x > 0x80000000u);
        unsigned m1 = __ballot_sync(0xffffffffu, c1 && kk.y > 0x80000000u);
        unsigned m2 = __ballot_sync(0xffffffffu, c2 && kk.z > 0x80000000u);
        unsigned m3 = __ballot_sync(0xffffffffu, c3 && kk.w > 0x80000000u);
        int group = it * 8 + w;          // 128-column group, 0..63
        size_t base = (size_t)(group * 4) * N_ROWS + row;
        if (lane == 0) g_mask[base]              = m0;
        if (lane == 1) g_mask[base + N_ROWS]     = m1;
        if (lane == 2) g_mask[base + 2 * N_ROWS] = m2;
        if (lane == 3) g_mask[base + 3 * N_ROWS] = m3;
    }
}

// ---------------------------------------------------------------------------
// Kernel 3: column counts via ballot bit-transpose, then EMA.
// Block wc owns mask word-column wc; bit i <-> column (wc>>2)*128+4*i+(wc&3).
// ---------------------------------------------------------------------------
__global__ __launch_bounds__(256)
void dc_kernel(const float* __restrict__ dc, float* __restrict__ dcout) {
    __shared__ unsigned s[256];
    const int t = threadIdx.x, lane = t & 31, wi = t >> 5;
    const int wc = blockIdx.x;
    const unsigned* __restrict__ mp = g_mask + (size_t)wc * N_ROWS;

    unsigned cnt = 0;
    const int r0 = wi * 1024;
    for (int g = 0; g < 32; ++g) {
        unsigned word = mp[r0 + g * 32 + lane];
#pragma unroll
        for (int i = 0; i < 32; ++i) {
            unsigned bal = __ballot_sync(0xffffffffu, (word >> i) & 1u);
            if (lane == i) cnt += __popc(bal);
        }
    }
    s[t] = cnt;
    __syncthreads();
    if (t < 32) {
        unsigned tot = 0;
#pragma unroll
        for (int i = 0; i < 8; ++i) tot += s[i * 32 + t];
        int col = (wc >> 2) * 128 + 4 * t + (wc & 3);
        dcout[col] = 0.9f * dc[col] + 0.1f * (float)tot;
    }
}

// ---------------------------------------------------------------------------
extern "C" void kernel_launch(void* const* d_in, const int* in_sizes, int n_in,
                              void* d_out, int out_size) {
    const float* inputs = (const float*)d_in[0];
    const float* dc     = (const float*)d_in[1];
    if (n_in >= 2 && in_sizes[0] < in_sizes[1]) {
        const float* tmp = inputs; inputs = dc; dc = tmp;
    }
    float* out = (float*)d_out;

    boost_kernel<<<(F_COLS + 255) / 256, 256>>>(dc);

    const int smem_bytes = (8192 + 2048 + 512 + 256) * 4;   // 44032 B, 5 CTAs/SM
    topk_kernel<<<N_ROWS, 256, smem_bytes>>>(inputs, out);

    if (out_size >= (int)((size_t)N_ROWS * F_COLS + F_COLS)) {
        float* dcout = out + (size_t)N_ROWS * F_COLS;
        dc_kernel<<<256, 256>>>(dc, dcout);
    }
}

// round 16
// speedup vs baseline: 1.1925x; 1.0241x over previous
#include <cuda_runtime.h>
#include <cstdint>

#define N_ROWS 8192
#define F_COLS 8192
#define K_SEL  2867u
#define TPB    512

// Scratch (static __device__ arrays — allocation-free per harness rules)
__device__ __align__(16) float g_boost[F_COLS];
__device__ __align__(16) float g_rboost[F_COLS];
// Bit-interleaved positivity mask: word index wc in [0,256):
//   group = wc>>2, b = wc&3; bit i of word <-> column group*128 + 4*i + b
// stored transposed: g_mask[wc * N_ROWS + row]
__device__ unsigned g_mask[256 * N_ROWS];

// ---------------------------------------------------------------------------
// Kernel 1: boost = exp(BETA*(target - duty_cycle)) and its reciprocal
// ---------------------------------------------------------------------------
__global__ void boost_kernel(const float* __restrict__ dc) {
    int j = blockIdx.x * blockDim.x + threadIdx.x;
    if (j < F_COLS) {
        const float target = 2867.0f / 8192.0f;   // exact dyadic
        float b = expf(1.5f * (target - dc[j]));
        g_boost[j]  = b;
        g_rboost[j] = 1.0f / b;
    }
}

// Monotonic order-preserving key for float bits u.
__device__ __forceinline__ unsigned fkey(unsigned u) {
    return u ^ (((unsigned)((int)u >> 31)) | 0x80000000u);
}

// ---------------------------------------------------------------------------
// Radix-select over an UNPACKED 2048-bin u32 histogram (512-thread block;
// threads >= 256 only participate in the barriers): find bin B with
//   count(bins > B) < kr <= count(bins >= B);  writes B and residual rank.
// Defined for all inputs (kr > total -> bin 0, rank 1).
// ---------------------------------------------------------------------------
__device__ __forceinline__ void select_bin(const unsigned* __restrict__ hist,
                                           unsigned* __restrict__ part,
                                           unsigned kr,
                                           volatile unsigned* sh_bin,
                                           volatile unsigned* sh_kr) {
    int t = threadIdx.x;
    if (t == 0) { *sh_bin = 0; *sh_kr = 1; }
    if (t < 256) {
        unsigned s = 0;
#pragma unroll
        for (int i = 0; i < 8; ++i) s += hist[t * 8 + i];
        part[t] = s;
    }
    __syncthreads();

    if (t < 32) {
        unsigned c = 0;
#pragma unroll
        for (int i = 0; i < 8; ++i) c += part[t * 8 + i];
        unsigned v = c;
#pragma unroll
        for (int off = 1; off < 32; off <<= 1) {
            unsigned u = __shfl_down_sync(0xffffffffu, v, off);
            if (t + off < 32) v += u;
        }
        unsigned ab = __shfl_down_sync(0xffffffffu, v, 1);
        if (t == 31) ab = 0;
        unsigned m = __ballot_sync(0xffffffffu, v >= kr);
        if (m != 0u) {
            int L = 31 - __clz(m);
            if (t == L) {
                unsigned cum = ab;
                int bin = 0; unsigned krn = 1;
                for (int g = 7; g >= 0; --g) {
                    int gi = L * 8 + g;
                    unsigned pg = part[gi];
                    if (cum + pg >= kr) {
                        for (int b = 7; b >= 0; --b) {
                            int bi = gi * 8 + b;
                            unsigned hb = hist[bi];
                            if (cum + hb >= kr) { bin = bi; krn = kr - cum; break; }
                            cum += hb;
                        }
                        break;
                    }
                    cum += pg;
                }
                *sh_bin = (unsigned)bin;
                *sh_kr  = krn;
            }
        }
    }
    __syncthreads();
}

// ---------------------------------------------------------------------------
// Kernel 2: one CTA (512 threads) per row.
//  pass 1 : load row -> keys in smem, 2048-word atomic hist on bits 31..21
//  pass 2 : hist of bits 20..10 over threshold-bin keys, FUSED with
//           collection of those keys into a 512-entry list (~190 expected)
//  level 3: bits 9..0 over the list; overflow -> full sweep (adversarial only)
//  output : vectorized threshold write + bit-interleaved positivity mask
// ---------------------------------------------------------------------------
__global__ __launch_bounds__(TPB, 3)
void topk_kernel(const float* __restrict__ in, float* __restrict__ out) {
    extern __shared__ unsigned smem[];
    unsigned* keys = smem;            // 8192 words
    unsigned* hist = smem + 8192;     // 2048 words (unpacked u32 bins)
    unsigned* list = smem + 10240;    // 512 words
    unsigned* part = smem + 10752;    // 256 words
    __shared__ unsigned sh_bin, sh_kr, sh_cnt;

    const int t = threadIdx.x;
    const int lane = t & 31, w = t >> 5;
    const int row = blockIdx.x;

    reinterpret_cast<uint4*>(hist)[t] = make_uint4(0, 0, 0, 0);  // 512*16B = 8KB
    if (t == 0) sh_cnt = 0;
    __syncthreads();

    // ---- pass 1: read row, form keys, hist top 11 bits (unpacked)
    const float4* __restrict__ rowp =
        reinterpret_cast<const float4*>(in) + (size_t)row * (F_COLS / 4);
    const float4* __restrict__ bp = reinterpret_cast<const float4*>(g_boost);
#pragma unroll
    for (int it = 0; it < 4; ++it) {
        int i4 = it * TPB + t;
        float4 v = rowp[i4];
        float4 b = bp[i4];
        unsigned k0 = fkey(__float_as_uint(v.x * b.x));
        unsigned k1 = fkey(__float_as_uint(v.y * b.y));
        unsigned k2 = fkey(__float_as_uint(v.z * b.z));
        unsigned k3 = fkey(__float_as_uint(v.w * b.w));
        reinterpret_cast<uint4*>(keys)[i4] = make_uint4(k0, k1, k2, k3);
        atomicAdd(&hist[k0 >> 21], 1u);
        atomicAdd(&hist[k1 >> 21], 1u);
        atomicAdd(&hist[k2 >> 21], 1u);
        atomicAdd(&hist[k3 >> 21], 1u);
    }
    __syncthreads();

    select_bin(hist, part, K_SEL, &sh_bin, &sh_kr);
    const unsigned B1 = sh_bin, kr2 = sh_kr;

    // ---- pass 2 (fused with collect): bits 20..10 over keys matching B1
    reinterpret_cast<uint4*>(hist)[t] = make_uint4(0, 0, 0, 0);
    __syncthreads();
#pragma unroll
    for (int it = 0; it < 4; ++it) {
        uint4 kk = reinterpret_cast<const uint4*>(keys)[it * TPB + t];
        if ((kk.x >> 21) == B1) {
            atomicAdd(&hist[(kk.x >> 10) & 0x7FFu], 1u);
            unsigned p = atomicAdd(&sh_cnt, 1u); if (p < 512u) list[p] = kk.x;
        }
        if ((kk.y >> 21) == B1) {
            atomicAdd(&hist[(kk.y >> 10) & 0x7FFu], 1u);
            unsigned p = atomicAdd(&sh_cnt, 1u); if (p < 512u) list[p] = kk.y;
        }
        if ((kk.z >> 21) == B1) {
            atomicAdd(&hist[(kk.z >> 10) & 0x7FFu], 1u);
            unsigned p = atomicAdd(&sh_cnt, 1u); if (p < 512u) list[p] = kk.z;
        }
        if ((kk.w >> 21) == B1) {
            atomicAdd(&hist[(kk.w >> 10) & 0x7FFu], 1u);
            unsigned p = atomicAdd(&sh_cnt, 1u); if (p < 512u) list[p] = kk.w;
        }
    }
    __syncthreads();
    select_bin(hist, part, kr2, &sh_bin, &sh_kr);
    const unsigned pref22 = (B1 << 11) | sh_bin;
    const unsigned kr3 = sh_kr;
    const unsigned m = sh_cnt;

    // ---- level 3: bits 9..0 (1024 bins live; upper 1024 words stay 0)
    reinterpret_cast<uint4*>(hist)[t] = make_uint4(0, 0, 0, 0);
    __syncthreads();
    if (m <= 512u) {
        // list holds ALL threshold-bin candidates -> exact
        for (unsigned i = t; i < m; i += TPB) {
            unsigned k = list[i];
            if ((k >> 10) == pref22) atomicAdd(&hist[k & 0x3FFu], 1u);
        }
    } else {
        // fallback: full sweep (adversarial inputs only)
#pragma unroll
        for (int it = 0; it < 4; ++it) {
            uint4 kk = reinterpret_cast<const uint4*>(keys)[it * TPB + t];
            if ((kk.x >> 10) == pref22) atomicAdd(&hist[kk.x & 0x3FFu], 1u);
            if ((kk.y >> 10) == pref22) atomicAdd(&hist[kk.y & 0x3FFu], 1u);
            if ((kk.z >> 10) == pref22) atomicAdd(&hist[kk.z & 0x3FFu], 1u);
            if ((kk.w >> 10) == pref22) atomicAdd(&hist[kk.w & 0x3FFu], 1u);
        }
    }
    __syncthreads();
    select_bin(hist, part, kr3, &sh_bin, &sh_kr);
    const unsigned T = (pref22 << 10) | sh_bin;    // k-th largest key

    // ---- output pass (vectorized): threshold, reconstruct, interleaved mask
    float4* __restrict__ orow =
        reinterpret_cast<float4*>(out) + (size_t)row * (F_COLS / 4);
    const float4* __restrict__ rbp = reinterpret_cast<const float4*>(g_rboost);
#pragma unroll
    for (int it = 0; it < 4; ++it) {
        int i4 = it * TPB + t;
        uint4 kk = reinterpret_cast<const uint4*>(keys)[i4];
        float4 rb = rbp[i4];
        bool c0 = kk.x >= T, c1 = kk.y >= T, c2 = kk.z >= T, c3 = kk.w >= T;
        // inverse key: bits = k ^ (0x80000000 | ~((int)k>>31))
        unsigned b0 = kk.x ^ (0x80000000u | ~(unsigned)((int)kk.x >> 31));
        unsigned b1 = kk.y ^ (0x80000000u | ~(unsigned)((int)kk.y >> 31));
        unsigned b2 = kk.z ^ (0x80000000u | ~(unsigned)((int)kk.z >> 31));
        unsigned b3 = kk.w ^ (0x80000000u | ~(unsigned)((int)kk.w >> 31));
        float4 o;
        o.x = c0 ? __uint_as_float(b0) * rb.x : 0.0f;
        o.y = c1 ? __uint_as_float(b1) * rb.y : 0.0f;
        o.z = c2 ? __uint_as_float(b2) * rb.z : 0.0f;
        o.w = c3 ? __uint_as_float(b3) * rb.w : 0.0f;
        orow[i4] = o;
        unsigned m0 = __ballot_sync(0xffffffffu, c0 && kk.x > 0x80000000u);
        unsigned m1 = __ballot_sync(0xffffffffu, c1 && kk.y > 0x80000000u);
        unsigned m2 = __ballot_sync(0xffffffffu, c2 && kk.z > 0x80000000u);
        unsigned m3 = __ballot_sync(0xffffffffu, c3 && kk.w > 0x80000000u);
        int group = it * 16 + w;         // 128-column group, 0..63
        size_t base = (size_t)(group * 4) * N_ROWS + row;
        if (lane == 0) g_mask[base]              = m0;
        if (lane == 1) g_mask[base + N_ROWS]     = m1;
        if (lane == 2) g_mask[base + 2 * N_ROWS] = m2;
        if (lane == 3) g_mask[base + 3 * N_ROWS] = m3;
    }
}

// ---------------------------------------------------------------------------
// Kernel 3: column counts via ballot bit-transpose, then EMA.
// Block wc owns mask word-column wc; bit i <-> column (wc>>2)*128+4*i+(wc&3).
// ---------------------------------------------------------------------------
__global__ __launch_bounds__(256)
void dc_kernel(const float* __restrict__ dc, float* __restrict__ dcout) {
    __shared__ unsigned s[256];
    const int t = threadIdx.x, lane = t & 31, wi = t >> 5;
    const int wc = blockIdx.x;
    const unsigned* __restrict__ mp = g_mask + (size_t)wc * N_ROWS;

    unsigned cnt = 0;
    const int r0 = wi * 1024;
    for (int g = 0; g < 32; ++g) {
        unsigned word = mp[r0 + g * 32 + lane];
#pragma unroll
        for (int i = 0; i < 32; ++i) {
            unsigned bal = __ballot_sync(0xffffffffu, (word >> i) & 1u);
            if (lane == i) cnt += __popc(bal);
        }
    }
    s[t] = cnt;
    __syncthreads();
    if (t < 32) {
        unsigned tot = 0;
#pragma unroll
        for (int i = 0; i < 8; ++i) tot += s[i * 32 + t];
        int col = (wc >> 2) * 128 + 4 * t + (wc & 3);
        dcout[col] = 0.9f * dc[col] + 0.1f * (float)tot;
    }
}

// ---------------------------------------------------------------------------
extern "C" void kernel_launch(void* const* d_in, const int* in_sizes, int n_in,
                              void* d_out, int out_size) {
    const float* inputs = (const float*)d_in[0];
    const float* dc     = (const float*)d_in[1];
    if (n_in >= 2 && in_sizes[0] < in_sizes[1]) {
        const float* tmp = inputs; inputs = dc; dc = tmp;
    }
    float* out = (float*)d_out;

    boost_kernel<<<(F_COLS + 255) / 256, 256>>>(dc);

    const int smem_bytes = (8192 + 2048 + 512 + 256) * 4;   // 44032 B
    topk_kernel<<<N_ROWS, TPB, smem_bytes>>>(inputs, out);

    if (out_size >= (int)((size_t)N_ROWS * F_COLS + F_COLS)) {
        float* dcout = out + (size_t)N_ROWS * F_COLS;
        dc_kernel<<<256, 256>>>(dc, dcout);
    }
}

// round 17
// speedup vs baseline: 1.3454x; 1.1281x over previous
#include <cuda_runtime.h>
#include <cstdint>

#define N_ROWS 8192
#define F_COLS 8192
#define K_SEL  2867u
#define TPB    512

// Scratch (static __device__ arrays — allocation-free per harness rules)
__device__ __align__(16) float g_boost[F_COLS];
__device__ __align__(16) float g_rboost[F_COLS];
__device__ unsigned g_bflag[32];     // per-block "dc differs from dc[0]" flags
// Bit-interleaved positivity mask: word index wc in [0,256):
//   group = wc>>2, b = wc&3; bit i of word <-> column group*128 + 4*i + b
// stored transposed: g_mask[wc * N_ROWS + row]
__device__ unsigned g_mask[256 * N_ROWS];

// ---------------------------------------------------------------------------
// Kernel 1: boost tables + per-block uniformity flag (dc[j] == dc[0] ?)
// ---------------------------------------------------------------------------
__global__ void boost_kernel(const float* __restrict__ dc) {
    int j = blockIdx.x * blockDim.x + threadIdx.x;
    const float target = 2867.0f / 8192.0f;   // exact dyadic
    float dc0 = dc[0];
    float d = dc[j];
    float b = expf(1.5f * (target - d));
    g_boost[j]  = b;
    g_rboost[j] = 1.0f / b;
    int differs = __syncthreads_or(__float_as_uint(d) != __float_as_uint(dc0));
    if (threadIdx.x == 0) g_bflag[blockIdx.x] = (unsigned)differs;
}

// Monotonic order-preserving key for float bits u.
__device__ __forceinline__ unsigned fkey(unsigned u) {
    return u ^ (((unsigned)((int)u >> 31)) | 0x80000000u);
}

// ---------------------------------------------------------------------------
// Radix-select over an UNPACKED 2048-bin u32 histogram (512-thread block;
// threads >= 256 only participate in the barriers): find bin B with
//   count(bins > B) < kr <= count(bins >= B);  writes B and residual rank.
// Defined for all inputs (kr > total -> bin 0, rank 1).
// ---------------------------------------------------------------------------
__device__ __forceinline__ void select_bin(const unsigned* __restrict__ hist,
                                           unsigned* __restrict__ part,
                                           unsigned kr,
                                           volatile unsigned* sh_bin,
                                           volatile unsigned* sh_kr) {
    int t = threadIdx.x;
    if (t == 0) { *sh_bin = 0; *sh_kr = 1; }
    if (t < 256) {
        unsigned s = 0;
#pragma unroll
        for (int i = 0; i < 8; ++i) s += hist[t * 8 + i];
        part[t] = s;
    }
    __syncthreads();

    if (t < 32) {
        unsigned c = 0;
#pragma unroll
        for (int i = 0; i < 8; ++i) c += part[t * 8 + i];
        unsigned v = c;
#pragma unroll
        for (int off = 1; off < 32; off <<= 1) {
            unsigned u = __shfl_down_sync(0xffffffffu, v, off);
            if (t + off < 32) v += u;
        }
        unsigned ab = __shfl_down_sync(0xffffffffu, v, 1);
        if (t == 31) ab = 0;
        unsigned m = __ballot_sync(0xffffffffu, v >= kr);
        if (m != 0u) {
            int L = 31 - __clz(m);
            if (t == L) {
                unsigned cum = ab;
                int bin = 0; unsigned krn = 1;
                for (int g = 7; g >= 0; --g) {
                    int gi = L * 8 + g;
                    unsigned pg = part[gi];
                    if (cum + pg >= kr) {
                        for (int b = 7; b >= 0; --b) {
                            int bi = gi * 8 + b;
                            unsigned hb = hist[bi];
                            if (cum + hb >= kr) { bin = bi; krn = kr - cum; break; }
                            cum += hb;
                        }
                        break;
                    }
                    cum += pg;
                }
                *sh_bin = (unsigned)bin;
                *sh_kr  = krn;
            }
        }
    }
    __syncthreads();
}

// ---------------------------------------------------------------------------
// Kernel 2: one CTA (512 threads) per row.
//  FAST path (uniform duty_cycle -> constant boost): keys from RAW input
//  bits (ranking identical: x -> x*c monotone for c>0), exact values,
//  zero boost-table traffic.
//  SLOW path (general dc): R16 code, boosted keys + rboost reconstruction.
// ---------------------------------------------------------------------------
__global__ __launch_bounds__(TPB, 3)
void topk_kernel(const float* __restrict__ in, float* __restrict__ out) {
    extern __shared__ unsigned smem[];
    unsigned* keys = smem;            // 8192 words
    unsigned* hist = smem + 8192;     // 2048 words (unpacked u32 bins)
    unsigned* list = smem + 10240;    // 512 words
    unsigned* part = smem + 10752;    // 256 words
    __shared__ unsigned sh_bin, sh_kr, sh_cnt;

    const int t = threadIdx.x;
    const int lane = t & 31, w = t >> 5;
    const int row = blockIdx.x;

    // uniformity decision: every warp loads all 32 flags (L2 broadcast)
    const bool nonuni = __any_sync(0xffffffffu, g_bflag[lane] != 0u);

    reinterpret_cast<uint4*>(hist)[t] = make_uint4(0, 0, 0, 0);  // 8 KB
    if (t == 0) sh_cnt = 0;
    __syncthreads();

    // ---- pass 1: read row, form keys, hist top 11 bits (unpacked)
    const float4* __restrict__ rowp =
        reinterpret_cast<const float4*>(in) + (size_t)row * (F_COLS / 4);
    if (!nonuni) {
#pragma unroll
        for (int it = 0; it < 4; ++it) {
            int i4 = it * TPB + t;
            float4 v = rowp[i4];
            unsigned k0 = fkey(__float_as_uint(v.x));
            unsigned k1 = fkey(__float_as_uint(v.y));
            unsigned k2 = fkey(__float_as_uint(v.z));
            unsigned k3 = fkey(__float_as_uint(v.w));
            reinterpret_cast<uint4*>(keys)[i4] = make_uint4(k0, k1, k2, k3);
            atomicAdd(&hist[k0 >> 21], 1u);
            atomicAdd(&hist[k1 >> 21], 1u);
            atomicAdd(&hist[k2 >> 21], 1u);
            atomicAdd(&hist[k3 >> 21], 1u);
        }
    } else {
        const float4* __restrict__ bp = reinterpret_cast<const float4*>(g_boost);
#pragma unroll
        for (int it = 0; it < 4; ++it) {
            int i4 = it * TPB + t;
            float4 v = rowp[i4];
            float4 b = bp[i4];
            unsigned k0 = fkey(__float_as_uint(v.x * b.x));
            unsigned k1 = fkey(__float_as_uint(v.y * b.y));
            unsigned k2 = fkey(__float_as_uint(v.z * b.z));
            unsigned k3 = fkey(__float_as_uint(v.w * b.w));
            reinterpret_cast<uint4*>(keys)[i4] = make_uint4(k0, k1, k2, k3);
            atomicAdd(&hist[k0 >> 21], 1u);
            atomicAdd(&hist[k1 >> 21], 1u);
            atomicAdd(&hist[k2 >> 21], 1u);
            atomicAdd(&hist[k3 >> 21], 1u);
        }
    }
    __syncthreads();

    select_bin(hist, part, K_SEL, &sh_bin, &sh_kr);
    const unsigned B1 = sh_bin, kr2 = sh_kr;

    // ---- pass 2 (fused with collect): bits 20..10 over keys matching B1
    reinterpret_cast<uint4*>(hist)[t] = make_uint4(0, 0, 0, 0);
    __syncthreads();
#pragma unroll
    for (int it = 0; it < 4; ++it) {
        uint4 kk = reinterpret_cast<const uint4*>(keys)[it * TPB + t];
        if ((kk.x >> 21) == B1) {
            atomicAdd(&hist[(kk.x >> 10) & 0x7FFu], 1u);
            unsigned p = atomicAdd(&sh_cnt, 1u); if (p < 512u) list[p] = kk.x;
        }
        if ((kk.y >> 21) == B1) {
            atomicAdd(&hist[(kk.y >> 10) & 0x7FFu], 1u);
            unsigned p = atomicAdd(&sh_cnt, 1u); if (p < 512u) list[p] = kk.y;
        }
        if ((kk.z >> 21) == B1) {
            atomicAdd(&hist[(kk.z >> 10) & 0x7FFu], 1u);
            unsigned p = atomicAdd(&sh_cnt, 1u); if (p < 512u) list[p] = kk.z;
        }
        if ((kk.w >> 21) == B1) {
            atomicAdd(&hist[(kk.w >> 10) & 0x7FFu], 1u);
            unsigned p = atomicAdd(&sh_cnt, 1u); if (p < 512u) list[p] = kk.w;
        }
    }
    __syncthreads();
    select_bin(hist, part, kr2, &sh_bin, &sh_kr);
    const unsigned pref22 = (B1 << 11) | sh_bin;
    const unsigned kr3 = sh_kr;
    const unsigned m = sh_cnt;

    // ---- level 3: bits 9..0 (1024 bins live; upper 1024 words stay 0)
    reinterpret_cast<uint4*>(hist)[t] = make_uint4(0, 0, 0, 0);
    __syncthreads();
    if (m <= 512u) {
        for (unsigned i = t; i < m; i += TPB) {
            unsigned k = list[i];
            if ((k >> 10) == pref22) atomicAdd(&hist[k & 0x3FFu], 1u);
        }
    } else {
#pragma unroll
        for (int it = 0; it < 4; ++it) {
            uint4 kk = reinterpret_cast<const uint4*>(keys)[it * TPB + t];
            if ((kk.x >> 10) == pref22) atomicAdd(&hist[kk.x & 0x3FFu], 1u);
            if ((kk.y >> 10) == pref22) atomicAdd(&hist[kk.y & 0x3FFu], 1u);
            if ((kk.z >> 10) == pref22) atomicAdd(&hist[kk.z & 0x3FFu], 1u);
            if ((kk.w >> 10) == pref22) atomicAdd(&hist[kk.w & 0x3FFu], 1u);
        }
    }
    __syncthreads();
    select_bin(hist, part, kr3, &sh_bin, &sh_kr);
    const unsigned T = (pref22 << 10) | sh_bin;    // k-th largest key

    // ---- output pass (vectorized): threshold, values, interleaved mask
    float4* __restrict__ orow =
        reinterpret_cast<float4*>(out) + (size_t)row * (F_COLS / 4);
    if (!nonuni) {
        // FAST: keys ARE raw bits (encoded) -> exact original values
#pragma unroll
        for (int it = 0; it < 4; ++it) {
            int i4 = it * TPB + t;
            uint4 kk = reinterpret_cast<const uint4*>(keys)[i4];
            bool c0 = kk.x >= T, c1 = kk.y >= T, c2 = kk.z >= T, c3 = kk.w >= T;
            unsigned b0 = kk.x ^ (0x80000000u | ~(unsigned)((int)kk.x >> 31));
            unsigned b1 = kk.y ^ (0x80000000u | ~(unsigned)((int)kk.y >> 31));
            unsigned b2 = kk.z ^ (0x80000000u | ~(unsigned)((int)kk.z >> 31));
            unsigned b3 = kk.w ^ (0x80000000u | ~(unsigned)((int)kk.w >> 31));
            float4 o;
            o.x = c0 ? __uint_as_float(b0) : 0.0f;
            o.y = c1 ? __uint_as_float(b1) : 0.0f;
            o.z = c2 ? __uint_as_float(b2) : 0.0f;
            o.w = c3 ? __uint_as_float(b3) : 0.0f;
            orow[i4] = o;
            unsigned m0 = __ballot_sync(0xffffffffu, c0 && kk.x > 0x80000000u);
            unsigned m1 = __ballot_sync(0xffffffffu, c1 && kk.y > 0x80000000u);
            unsigned m2 = __ballot_sync(0xffffffffu, c2 && kk.z > 0x80000000u);
            unsigned m3 = __ballot_sync(0xffffffffu, c3 && kk.w > 0x80000000u);
            int group = it * 16 + w;         // 128-column group, 0..63
            size_t base = (size_t)(group * 4) * N_ROWS + row;
            if (lane == 0) g_mask[base]              = m0;
            if (lane == 1) g_mask[base + N_ROWS]     = m1;
            if (lane == 2) g_mask[base + 2 * N_ROWS] = m2;
            if (lane == 3) g_mask[base + 3 * N_ROWS] = m3;
        }
    } else {
        const float4* __restrict__ rbp = reinterpret_cast<const float4*>(g_rboost);
#pragma unroll
        for (int it = 0; it < 4; ++it) {
            int i4 = it * TPB + t;
            uint4 kk = reinterpret_cast<const uint4*>(keys)[i4];
            float4 rb = rbp[i4];
            bool c0 = kk.x >= T, c1 = kk.y >= T, c2 = kk.z >= T, c3 = kk.w >= T;
            unsigned b0 = kk.x ^ (0x80000000u | ~(unsigned)((int)kk.x >> 31));
            unsigned b1 = kk.y ^ (0x80000000u | ~(unsigned)((int)kk.y >> 31));
            unsigned b2 = kk.z ^ (0x80000000u | ~(unsigned)((int)kk.z >> 31));
            unsigned b3 = kk.w ^ (0x80000000u | ~(unsigned)((int)kk.w >> 31));
            float4 o;
            o.x = c0 ? __uint_as_float(b0) * rb.x : 0.0f;
            o.y = c1 ? __uint_as_float(b1) * rb.y : 0.0f;
            o.z = c2 ? __uint_as_float(b2) * rb.z : 0.0f;
            o.w = c3 ? __uint_as_float(b3) * rb.w : 0.0f;
            orow[i4] = o;
            unsigned m0 = __ballot_sync(0xffffffffu, c0 && kk.x > 0x80000000u);
            unsigned m1 = __ballot_sync(0xffffffffu, c1 && kk.y > 0x80000000u);
            unsigned m2 = __ballot_sync(0xffffffffu, c2 && kk.z > 0x80000000u);
            unsigned m3 = __ballot_sync(0xffffffffu, c3 && kk.w > 0x80000000u);
            int group = it * 16 + w;
            size_t base = (size_t)(group * 4) * N_ROWS + row;
            if (lane == 0) g_mask[base]              = m0;
            if (lane == 1) g_mask[base + N_ROWS]     = m1;
            if (lane == 2) g_mask[base + 2 * N_ROWS] = m2;
            if (lane == 3) g_mask[base + 3 * N_ROWS] = m3;
        }
    }
}

// ---------------------------------------------------------------------------
// Kernel 3: column counts via ballot bit-transpose, then EMA.
// Block wc owns mask word-column wc; bit i <-> column (wc>>2)*128+4*i+(wc&3).
// ---------------------------------------------------------------------------
__global__ __launch_bounds__(256)
void dc_kernel(const float* __restrict__ dc, float* __restrict__ dcout) {
    __shared__ unsigned s[256];
    const int t = threadIdx.x, lane = t & 31, wi = t >> 5;
    const int wc = blockIdx.x;
    const unsigned* __restrict__ mp = g_mask + (size_t)wc * N_ROWS;

    unsigned cnt = 0;
    const int r0 = wi * 1024;
    for (int g = 0; g < 32; ++g) {
        unsigned word = mp[r0 + g * 32 + lane];
#pragma unroll
        for (int i = 0; i < 32; ++i) {
            unsigned bal = __ballot_sync(0xffffffffu, (word >> i) & 1u);
            if (lane == i) cnt += __popc(bal);
        }
    }
    s[t] = cnt;
    __syncthreads();
    if (t < 32) {
        unsigned tot = 0;
#pragma unroll
        for (int i = 0; i < 8; ++i) tot += s[i * 32 + t];
        int col = (wc >> 2) * 128 + 4 * t + (wc & 3);
        dcout[col] = 0.9f * dc[col] + 0.1f * (float)tot;
    }
}

// ---------------------------------------------------------------------------
extern "C" void kernel_launch(void* const* d_in, const int* in_sizes, int n_in,
                              void* d_out, int out_size) {
    const float* inputs = (const float*)d_in[0];
    const float* dc     = (const float*)d_in[1];
    if (n_in >= 2 && in_sizes[0] < in_sizes[1]) {
        const float* tmp = inputs; inputs = dc; dc = tmp;
    }
    float* out = (float*)d_out;

    boost_kernel<<<32, 256>>>(dc);

    const int smem_bytes = (8192 + 2048 + 512 + 256) * 4;   // 44032 B
    topk_kernel<<<N_ROWS, TPB, smem_bytes>>>(inputs, out);

    if (out_size >= (int)((size_t)N_ROWS * F_COLS + F_COLS)) {
        float* dcout = out + (size_t)N_ROWS * F_COLS;
        dc_kernel<<<256, 256>>>(dc, dcout);
    }
}